// round 7
// baseline (speedup 1.0000x reference)
#include <cuda_runtime.h>
#include <cuda_bf16.h>
#include <math.h>
#include <stdint.h>

// Problem constants
#define B_   4
#define T_   2048
#define S_   2048
#define DQ_  512
#define DKV_ 1024
#define H_   8
#define HD_  64

// Scratch buffers (allocation-free: __device__ globals)
__device__ float g_Q[B_ * T_ * DQ_];
__device__ float g_K[B_ * S_ * DQ_];
__device__ float g_V[B_ * S_ * DQ_];
__device__ float g_ctx[B_ * T_ * DQ_];

// ---------------------------------------------------------------------------
// Helpers
// ---------------------------------------------------------------------------
__device__ __forceinline__ uint32_t f2tf32(float f) {
    uint32_t r;
    asm("cvt.rna.tf32.f32 %0, %1;" : "=r"(r) : "f"(f));
    return r;
}
__device__ __forceinline__ uint32_t ldtf(const float* p) { return f2tf32(*p); }

__device__ __forceinline__ void mma_tf32(float d[4],
                                         uint32_t a0, uint32_t a1, uint32_t a2, uint32_t a3,
                                         uint32_t b0, uint32_t b1) {
    asm volatile(
        "mma.sync.aligned.m16n8k8.row.col.f32.tf32.tf32.f32 "
        "{%0,%1,%2,%3}, {%4,%5,%6,%7}, {%8,%9}, {%0,%1,%2,%3};\n"
        : "+f"(d[0]), "+f"(d[1]), "+f"(d[2]), "+f"(d[3])
        : "r"(a0), "r"(a1), "r"(a2), "r"(a3), "r"(b0), "r"(b1));
}

__device__ __forceinline__ void cp_async16(uint32_t s, const void* g) {
    asm volatile("cp.async.cg.shared.global [%0], [%1], 16;\n" :: "r"(s), "l"(g));
}
__device__ __forceinline__ void cp_commit() { asm volatile("cp.async.commit_group;\n" ::: "memory"); }
__device__ __forceinline__ void cp_wait0()  { asm volatile("cp.async.wait_group 0;\n" ::: "memory"); }

// ---------------------------------------------------------------------------
// Projections / output:  C[M,N] = A[M,K] @ W[K,N] + bias[N]
// Block 128x64, 4 warps (2x2), BK=32, cp.async double-buffered.
// ---------------------------------------------------------------------------
__global__ __launch_bounds__(128, 4) void gemm_bias_tc(
    const float* __restrict__ A, const float* __restrict__ W,
    const float* __restrict__ bias, float* __restrict__ C,
    int M, int N, int K)
{
    extern __shared__ float dsm[];
    float* As = dsm;                    // [2][128][36]
    float* Bs = dsm + 2 * 128 * 36;     // [2][32][68]
    const uint32_t abase = (uint32_t)__cvta_generic_to_shared(As);
    const uint32_t bbase = (uint32_t)__cvta_generic_to_shared(Bs);

    const int tid = threadIdx.x;
    const int wid = tid >> 5, lane = tid & 31;
    const int g = lane >> 2, tg = lane & 3;
    const int bm = blockIdx.y * 128, bn = blockIdx.x * 64;
    const int wm = (wid >> 1) * 64, wn = (wid & 1) * 32;

    float acc[4][4][4];
    #pragma unroll
    for (int mt = 0; mt < 4; mt++)
        #pragma unroll
        for (int nt = 0; nt < 4; nt++)
            #pragma unroll
            for (int r = 0; r < 4; r++) acc[mt][nt][r] = 0.f;

    auto load_stage = [&](int buf, int k0) {
        uint32_t ab = abase + (uint32_t)buf * 128 * 36 * 4;
        #pragma unroll
        for (int i = tid; i < 128 * 8; i += 128) {
            int r = i >> 3, seg = i & 7;
            cp_async16(ab + (r * 36 + seg * 4) * 4,
                       A + (size_t)(bm + r) * K + k0 + seg * 4);
        }
        uint32_t bb = bbase + (uint32_t)buf * 32 * 68 * 4;
        #pragma unroll
        for (int i = tid; i < 32 * 16; i += 128) {
            int r = i >> 4, seg = i & 15;
            cp_async16(bb + (r * 68 + seg * 4) * 4,
                       W + (size_t)(k0 + r) * N + bn + seg * 4);
        }
        cp_commit();
    };

    load_stage(0, 0);
    int buf = 0;
    for (int k0 = 0; k0 < K; k0 += 32, buf ^= 1) {
        cp_wait0();
        __syncthreads();
        if (k0 + 32 < K) load_stage(buf ^ 1, k0 + 32);

        const float* Ab = As + buf * 128 * 36;
        const float* Bb = Bs + buf * 32 * 68;
        #pragma unroll
        for (int ks = 0; ks < 4; ks++) {
            const int kk = ks * 8;
            uint32_t a[4][4], bf[4][2];
            #pragma unroll
            for (int mt = 0; mt < 4; mt++) {
                int mr = wm + mt * 16;
                a[mt][0] = ldtf(Ab + (mr + g) * 36 + kk + tg);
                a[mt][1] = ldtf(Ab + (mr + g + 8) * 36 + kk + tg);
                a[mt][2] = ldtf(Ab + (mr + g) * 36 + kk + tg + 4);
                a[mt][3] = ldtf(Ab + (mr + g + 8) * 36 + kk + tg + 4);
            }
            #pragma unroll
            for (int nt = 0; nt < 4; nt++) {
                int nc = wn + nt * 8 + g;
                bf[nt][0] = ldtf(Bb + (kk + tg) * 68 + nc);
                bf[nt][1] = ldtf(Bb + (kk + tg + 4) * 68 + nc);
            }
            #pragma unroll
            for (int mt = 0; mt < 4; mt++)
                #pragma unroll
                for (int nt = 0; nt < 4; nt++)
                    mma_tf32(acc[mt][nt], a[mt][0], a[mt][1], a[mt][2], a[mt][3],
                             bf[nt][0], bf[nt][1]);
        }
    }

    #pragma unroll
    for (int mt = 0; mt < 4; mt++) {
        #pragma unroll
        for (int nt = 0; nt < 4; nt++) {
            int n0 = bn + wn + nt * 8 + tg * 2;
            float b0v = bias[n0], b1v = bias[n0 + 1];
            int r0 = bm + wm + mt * 16 + g;
            C[(size_t)r0 * N + n0]           = acc[mt][nt][0] + b0v;
            C[(size_t)r0 * N + n0 + 1]       = acc[mt][nt][1] + b1v;
            C[(size_t)(r0 + 8) * N + n0]     = acc[mt][nt][2] + b0v;
            C[(size_t)(r0 + 8) * N + n0 + 1] = acc[mt][nt][3] + b1v;
        }
    }
}

// ---------------------------------------------------------------------------
// Scores: attn[b,h,t,s] = (Q.K)/8 + mask, kpm==0 -> -inf
// Block 128(t) x 128(s), 8 warps (2x4), single-shot K=64.
// smem holds TF32 BITS in pair-interleaved layout: within each k-group of 8,
// the fragment pair (k, k+4) is stored adjacently at columns (k&7 base):
// element pair j of group c lives at column c*8 + 2j (+1). -> LDS.64, zero
// cvt in the mainloop.
// ROW STRIDE 72 floats: 64 data + 8 pad. 72 mod 32 == 8, so the 16-lane
// phase pattern {g*8} x {2*tg} covers 16 distinct even banks -> conflict-free
// LDS.64. (Stride 40 in the previous round had the same residue but could
// not hold 64 columns -> OOB.)
// smem: Qs[128][72] + Ks[128][72] = 73728 B.
// ---------------------------------------------------------------------------
#define SROW 72

__global__ __launch_bounds__(256, 2) void score_tc(
    const float* __restrict__ Q, const float* __restrict__ Kp,
    const float* __restrict__ attn_mask, const int* __restrict__ kpm,
    float* __restrict__ attn)
{
    extern __shared__ float dsm[];
    float* Qs = dsm;                // [128][SROW] tf32 bits, permuted
    float* Ks = dsm + 128 * SROW;   // [128][SROW] n-major: [s][d], permuted

    const int tid = threadIdx.x;
    const int wid = tid >> 5, lane = tid & 31;
    const int g = lane >> 2, tg = lane & 3;
    const int bh = blockIdx.z;
    const int b = bh >> 3, h = bh & 7;
    const int t0 = blockIdx.y * 128, s0 = blockIdx.x * 128;
    const int wm = (wid >> 2) * 64, wn = (wid & 3) * 32;

    // Load + convert + permute. 8 threads per row, each thread owns 8 consecutive k.
    {
        const int r_in = tid >> 3;       // 0..31
        const int c    = tid & 7;        // k-chunk: k = c*8 .. c*8+7
        #pragma unroll
        for (int p = 0; p < 4; p++) {
            int r = p * 32 + r_in;
            const float4* qsrc = (const float4*)(Q + (size_t)(b * T_ + t0 + r) * DQ_ + h * HD_ + c * 8);
            const float4* ksrc = (const float4*)(Kp + (size_t)(b * S_ + s0 + r) * DQ_ + h * HD_ + c * 8);
            float4 q0 = qsrc[0], q1 = qsrc[1];
            float4 k0 = ksrc[0], k1 = ksrc[1];
            uint2* qdst = (uint2*)(Qs + r * SROW + c * 8);
            uint2* kdst = (uint2*)(Ks + r * SROW + c * 8);
            qdst[0] = make_uint2(f2tf32(q0.x), f2tf32(q1.x));
            qdst[1] = make_uint2(f2tf32(q0.y), f2tf32(q1.y));
            qdst[2] = make_uint2(f2tf32(q0.z), f2tf32(q1.z));
            qdst[3] = make_uint2(f2tf32(q0.w), f2tf32(q1.w));
            kdst[0] = make_uint2(f2tf32(k0.x), f2tf32(k1.x));
            kdst[1] = make_uint2(f2tf32(k0.y), f2tf32(k1.y));
            kdst[2] = make_uint2(f2tf32(k0.z), f2tf32(k1.z));
            kdst[3] = make_uint2(f2tf32(k0.w), f2tf32(k1.w));
        }
    }
    __syncthreads();

    float acc[4][4][4];
    #pragma unroll
    for (int mt = 0; mt < 4; mt++)
        #pragma unroll
        for (int nt = 0; nt < 4; nt++)
            #pragma unroll
            for (int r = 0; r < 4; r++) acc[mt][nt][r] = 0.f;

    #pragma unroll
    for (int ks = 0; ks < 8; ks++) {
        const int cb = ks * 8 + 2 * tg;   // column of pair (tg, tg+4) in this k-group
        uint2 a[4][2], bf[4];
        #pragma unroll
        for (int mt = 0; mt < 4; mt++) {
            int mr = wm + mt * 16;
            a[mt][0] = *(const uint2*)(Qs + (mr + g) * SROW + cb);       // (a0, a2)
            a[mt][1] = *(const uint2*)(Qs + (mr + g + 8) * SROW + cb);   // (a1, a3)
        }
        #pragma unroll
        for (int nt = 0; nt < 4; nt++) {
            int nc = wn + nt * 8 + g;
            bf[nt] = *(const uint2*)(Ks + nc * SROW + cb);               // (b0, b1)
        }
        #pragma unroll
        for (int mt = 0; mt < 4; mt++)
            #pragma unroll
            for (int nt = 0; nt < 4; nt++)
                mma_tf32(acc[mt][nt], a[mt][0].x, a[mt][1].x, a[mt][0].y, a[mt][1].y,
                         bf[nt].x, bf[nt].y);
    }

    // Epilogue: scale + mask + kpm
    #pragma unroll
    for (int mt = 0; mt < 4; mt++) {
        #pragma unroll
        for (int nt = 0; nt < 4; nt++) {
            int s = s0 + wn + nt * 8 + tg * 2;
            int kp0 = kpm[b * S_ + s], kp1 = kpm[b * S_ + s + 1];
            int t = t0 + wm + mt * 16 + g;
            #pragma unroll
            for (int half = 0; half < 2; half++) {
                int tr = t + half * 8;
                float v0 = acc[mt][nt][half * 2]     * 0.125f + attn_mask[(size_t)tr * S_ + s];
                float v1 = acc[mt][nt][half * 2 + 1] * 0.125f + attn_mask[(size_t)tr * S_ + s + 1];
                if (kp0 == 0) v0 = -INFINITY;
                if (kp1 == 0) v1 = -INFINITY;
                attn[((size_t)bh * T_ + tr) * S_ + s]     = v0;
                attn[((size_t)bh * T_ + tr) * S_ + s + 1] = v1;
            }
        }
    }
}

// ---------------------------------------------------------------------------
// In-place row softmax over S=2048.
// ---------------------------------------------------------------------------
__global__ __launch_bounds__(256) void softmax_kernel(float* __restrict__ attn)
{
    size_t row = blockIdx.x;
    float* p = attn + row * (size_t)S_;
    int tid = threadIdx.x;

    float v[8];
    #pragma unroll
    for (int i = 0; i < 8; i++) v[i] = p[tid + 256 * i];

    float m = v[0];
    #pragma unroll
    for (int i = 1; i < 8; i++) m = fmaxf(m, v[i]);
    #pragma unroll
    for (int o = 16; o > 0; o >>= 1) m = fmaxf(m, __shfl_xor_sync(0xffffffffu, m, o));

    __shared__ float red[8];
    if ((tid & 31) == 0) red[tid >> 5] = m;
    __syncthreads();
    if (tid < 32) {
        float x = (tid < 8) ? red[tid] : -INFINITY;
        #pragma unroll
        for (int o = 4; o > 0; o >>= 1) x = fmaxf(x, __shfl_xor_sync(0xffffffffu, x, o));
        if (tid == 0) red[0] = x;
    }
    __syncthreads();
    m = red[0];
    __syncthreads();

    float s = 0.f;
    #pragma unroll
    for (int i = 0; i < 8; i++) { v[i] = __expf(v[i] - m); s += v[i]; }
    #pragma unroll
    for (int o = 16; o > 0; o >>= 1) s += __shfl_xor_sync(0xffffffffu, s, o);
    if ((tid & 31) == 0) red[tid >> 5] = s;
    __syncthreads();
    if (tid < 32) {
        float x = (tid < 8) ? red[tid] : 0.f;
        #pragma unroll
        for (int o = 4; o > 0; o >>= 1) x += __shfl_xor_sync(0xffffffffu, x, o);
        if (tid == 0) red[0] = x;
    }
    __syncthreads();
    float inv = 1.0f / red[0];

    #pragma unroll
    for (int i = 0; i < 8; i++) p[tid + 256 * i] = v[i] * inv;
}

// ---------------------------------------------------------------------------
// ctx[b,t,h,:] = attn[b,h,t,:] @ V[b,:,h,:]
// Block 128(t) x 64(d), 4 warps (2x2), BK=32 over S, cp.async double-buffered.
// ---------------------------------------------------------------------------
__global__ __launch_bounds__(128, 4) void av_tc(
    const float* __restrict__ attn, const float* __restrict__ Vp,
    float* __restrict__ ctx)
{
    extern __shared__ float dsm[];
    float* As = dsm;                    // [2][128][36]
    float* Bs = dsm + 2 * 128 * 36;     // [2][32][68]
    const uint32_t abase = (uint32_t)__cvta_generic_to_shared(As);
    const uint32_t bbase = (uint32_t)__cvta_generic_to_shared(Bs);

    const int tid = threadIdx.x;
    const int wid = tid >> 5, lane = tid & 31;
    const int g = lane >> 2, tg = lane & 3;
    const int bh = blockIdx.y;
    const int b = bh >> 3, h = bh & 7;
    const int t0 = blockIdx.x * 128;
    const int wm = (wid >> 1) * 64, wn = (wid & 1) * 32;

    const float* arow = attn + ((size_t)bh * T_ + t0) * S_;

    float acc[4][4][4];
    #pragma unroll
    for (int mt = 0; mt < 4; mt++)
        #pragma unroll
        for (int nt = 0; nt < 4; nt++)
            #pragma unroll
            for (int r = 0; r < 4; r++) acc[mt][nt][r] = 0.f;

    auto load_stage = [&](int buf, int k0) {
        uint32_t ab = abase + (uint32_t)buf * 128 * 36 * 4;
        #pragma unroll
        for (int i = tid; i < 128 * 8; i += 128) {
            int r = i >> 3, seg = i & 7;
            cp_async16(ab + (r * 36 + seg * 4) * 4,
                       arow + (size_t)r * S_ + k0 + seg * 4);
        }
        uint32_t bb = bbase + (uint32_t)buf * 32 * 68 * 4;
        #pragma unroll
        for (int i = tid; i < 32 * 16; i += 128) {
            int r = i >> 4, seg = i & 15;
            cp_async16(bb + (r * 68 + seg * 4) * 4,
                       Vp + (size_t)(b * S_ + k0 + r) * DQ_ + h * HD_ + seg * 4);
        }
        cp_commit();
    };

    load_stage(0, 0);
    int buf = 0;
    for (int k0 = 0; k0 < S_; k0 += 32, buf ^= 1) {
        cp_wait0();
        __syncthreads();
        if (k0 + 32 < S_) load_stage(buf ^ 1, k0 + 32);

        const float* Ab = As + buf * 128 * 36;
        const float* Bb = Bs + buf * 32 * 68;
        #pragma unroll
        for (int ks = 0; ks < 4; ks++) {
            const int kk = ks * 8;
            uint32_t a[4][4], bf[4][2];
            #pragma unroll
            for (int mt = 0; mt < 4; mt++) {
                int mr = wm + mt * 16;
                a[mt][0] = ldtf(Ab + (mr + g) * 36 + kk + tg);
                a[mt][1] = ldtf(Ab + (mr + g + 8) * 36 + kk + tg);
                a[mt][2] = ldtf(Ab + (mr + g) * 36 + kk + tg + 4);
                a[mt][3] = ldtf(Ab + (mr + g + 8) * 36 + kk + tg + 4);
            }
            #pragma unroll
            for (int nt = 0; nt < 4; nt++) {
                int nc = wn + nt * 8 + g;
                bf[nt][0] = ldtf(Bb + (kk + tg) * 68 + nc);
                bf[nt][1] = ldtf(Bb + (kk + tg + 4) * 68 + nc);
            }
            #pragma unroll
            for (int mt = 0; mt < 4; mt++)
                #pragma unroll
                for (int nt = 0; nt < 4; nt++)
                    mma_tf32(acc[mt][nt], a[mt][0], a[mt][1], a[mt][2], a[mt][3],
                             bf[nt][0], bf[nt][1]);
        }
    }

    #pragma unroll
    for (int mt = 0; mt < 4; mt++) {
        #pragma unroll
        for (int nt = 0; nt < 4; nt++) {
            int d0 = wn + nt * 8 + tg * 2;
            int t = t0 + wm + mt * 16 + g;
            ctx[(size_t)(b * T_ + t) * DQ_ + h * HD_ + d0]         = acc[mt][nt][0];
            ctx[(size_t)(b * T_ + t) * DQ_ + h * HD_ + d0 + 1]     = acc[mt][nt][1];
            ctx[(size_t)(b * T_ + t + 8) * DQ_ + h * HD_ + d0]     = acc[mt][nt][2];
            ctx[(size_t)(b * T_ + t + 8) * DQ_ + h * HD_ + d0 + 1] = acc[mt][nt][3];
        }
    }
}

// ---------------------------------------------------------------------------
// Launch (single stream — no stream/event API anywhere)
// ---------------------------------------------------------------------------
extern "C" void kernel_launch(void* const* d_in, const int* in_sizes, int n_in,
                              void* d_out, int out_size)
{
    const float* query     = (const float*)d_in[0];
    const float* key       = (const float*)d_in[1];
    const float* value     = (const float*)d_in[2];
    const int*   kpm       = (const int*)  d_in[3];
    const float* attn_mask = (const float*)d_in[4];
    const float* Wq = (const float*)d_in[5];
    const float* bq = (const float*)d_in[6];
    const float* Wk = (const float*)d_in[7];
    const float* bk = (const float*)d_in[8];
    const float* Wv = (const float*)d_in[9];
    const float* bv = (const float*)d_in[10];
    const float* Wo = (const float*)d_in[11];
    const float* bo = (const float*)d_in[12];

    float* out  = (float*)d_out;                        // [B,T,DQ]
    float* attn = out + (size_t)B_ * T_ * DQ_;          // [B,H,T,S]

    float *Qp, *Kp, *Vp, *Cp;
    cudaGetSymbolAddress((void**)&Qp, g_Q);
    cudaGetSymbolAddress((void**)&Kp, g_K);
    cudaGetSymbolAddress((void**)&Vp, g_V);
    cudaGetSymbolAddress((void**)&Cp, g_ctx);

    const int GEMM_SMEM  = (2 * 128 * 36 + 2 * 32 * 68) * 4;   // 54272
    const int SCORE_SMEM = (2 * 128 * SROW) * 4;                // 73728

    static int attr_done = 0;
    if (!attr_done) {
        cudaFuncSetAttribute(gemm_bias_tc, cudaFuncAttributeMaxDynamicSharedMemorySize, GEMM_SMEM);
        cudaFuncSetAttribute(score_tc,     cudaFuncAttributeMaxDynamicSharedMemorySize, SCORE_SMEM);
        cudaFuncSetAttribute(av_tc,        cudaFuncAttributeMaxDynamicSharedMemorySize, GEMM_SMEM);
        attr_done = 1;
    }

    const int M = B_ * T_;   // 8192

    // Projections (tf32 tensor cores, cp.async pipelined)
    gemm_bias_tc<<<dim3(DQ_ / 64, M / 128), 128, GEMM_SMEM>>>(query, Wq, bq, Qp, M, DQ_, DQ_);
    gemm_bias_tc<<<dim3(DQ_ / 64, M / 128), 128, GEMM_SMEM>>>(key,   Wk, bk, Kp, M, DQ_, DKV_);
    gemm_bias_tc<<<dim3(DQ_ / 64, M / 128), 128, GEMM_SMEM>>>(value, Wv, bv, Vp, M, DQ_, DKV_);

    // Scores + mask -> attn region of d_out
    score_tc<<<dim3(S_ / 128, T_ / 128, B_ * H_), 256, SCORE_SMEM>>>(Qp, Kp, attn_mask, kpm, attn);

    // Row softmax in place
    softmax_kernel<<<B_ * H_ * T_, 256>>>(attn);

    // attn @ V -> ctx
    av_tc<<<dim3(T_ / 128, B_ * H_), 128, GEMM_SMEM>>>(attn, Vp, Cp);

    // Output projection
    gemm_bias_tc<<<dim3(DQ_ / 64, M / 128), 128, GEMM_SMEM>>>(Cp, Wo, bo, out, M, DQ_, DQ_);
}

// round 8
// speedup vs baseline: 1.0258x; 1.0258x over previous
#include <cuda_runtime.h>
#include <cuda_bf16.h>
#include <math.h>
#include <stdint.h>

// Problem constants
#define B_   4
#define T_   2048
#define S_   2048
#define DQ_  512
#define DKV_ 1024
#define H_   8
#define HD_  64
#define NSB  16            // number of s-blocks in score grid (S_/128)

// Scratch buffers (allocation-free: __device__ globals)
__device__ float g_Q[B_ * T_ * DQ_];
__device__ float g_K[B_ * S_ * DQ_];
__device__ float g_V[B_ * S_ * DQ_];
__device__ float g_ctx[B_ * T_ * DQ_];
__device__ float g_psum[B_ * H_ * T_ * NSB];   // per-(row, s-block) partial sum of exp
__device__ float g_inv[B_ * H_ * T_];          // 1 / full row sum

// ---------------------------------------------------------------------------
// Helpers
// ---------------------------------------------------------------------------
__device__ __forceinline__ uint32_t f2tf32(float f) {
    uint32_t r;
    asm("cvt.rna.tf32.f32 %0, %1;" : "=r"(r) : "f"(f));
    return r;
}
__device__ __forceinline__ uint32_t ldtf(const float* p) { return f2tf32(*p); }

__device__ __forceinline__ void mma_tf32(float d[4],
                                         uint32_t a0, uint32_t a1, uint32_t a2, uint32_t a3,
                                         uint32_t b0, uint32_t b1) {
    asm volatile(
        "mma.sync.aligned.m16n8k8.row.col.f32.tf32.tf32.f32 "
        "{%0,%1,%2,%3}, {%4,%5,%6,%7}, {%8,%9}, {%0,%1,%2,%3};\n"
        : "+f"(d[0]), "+f"(d[1]), "+f"(d[2]), "+f"(d[3])
        : "r"(a0), "r"(a1), "r"(a2), "r"(a3), "r"(b0), "r"(b1));
}

__device__ __forceinline__ void cp_async16(uint32_t s, const void* g) {
    asm volatile("cp.async.cg.shared.global [%0], [%1], 16;\n" :: "r"(s), "l"(g));
}
__device__ __forceinline__ void cp_commit() { asm volatile("cp.async.commit_group;\n" ::: "memory"); }
__device__ __forceinline__ void cp_wait0()  { asm volatile("cp.async.wait_group 0;\n" ::: "memory"); }

// ---------------------------------------------------------------------------
// Projections / output:  C[M,N] = A[M,K] @ W[K,N] + bias[N]
// Block 128x64, 4 warps (2x2), BK=32, cp.async double-buffered. (unchanged)
// ---------------------------------------------------------------------------
__global__ __launch_bounds__(128, 4) void gemm_bias_tc(
    const float* __restrict__ A, const float* __restrict__ W,
    const float* __restrict__ bias, float* __restrict__ C,
    int M, int N, int K)
{
    extern __shared__ float dsm[];
    float* As = dsm;                    // [2][128][36]
    float* Bs = dsm + 2 * 128 * 36;     // [2][32][68]
    const uint32_t abase = (uint32_t)__cvta_generic_to_shared(As);
    const uint32_t bbase = (uint32_t)__cvta_generic_to_shared(Bs);

    const int tid = threadIdx.x;
    const int wid = tid >> 5, lane = tid & 31;
    const int g = lane >> 2, tg = lane & 3;
    const int bm = blockIdx.y * 128, bn = blockIdx.x * 64;
    const int wm = (wid >> 1) * 64, wn = (wid & 1) * 32;

    float acc[4][4][4];
    #pragma unroll
    for (int mt = 0; mt < 4; mt++)
        #pragma unroll
        for (int nt = 0; nt < 4; nt++)
            #pragma unroll
            for (int r = 0; r < 4; r++) acc[mt][nt][r] = 0.f;

    auto load_stage = [&](int buf, int k0) {
        uint32_t ab = abase + (uint32_t)buf * 128 * 36 * 4;
        #pragma unroll
        for (int i = tid; i < 128 * 8; i += 128) {
            int r = i >> 3, seg = i & 7;
            cp_async16(ab + (r * 36 + seg * 4) * 4,
                       A + (size_t)(bm + r) * K + k0 + seg * 4);
        }
        uint32_t bb = bbase + (uint32_t)buf * 32 * 68 * 4;
        #pragma unroll
        for (int i = tid; i < 32 * 16; i += 128) {
            int r = i >> 4, seg = i & 15;
            cp_async16(bb + (r * 68 + seg * 4) * 4,
                       W + (size_t)(k0 + r) * N + bn + seg * 4);
        }
        cp_commit();
    };

    load_stage(0, 0);
    int buf = 0;
    for (int k0 = 0; k0 < K; k0 += 32, buf ^= 1) {
        cp_wait0();
        __syncthreads();
        if (k0 + 32 < K) load_stage(buf ^ 1, k0 + 32);

        const float* Ab = As + buf * 128 * 36;
        const float* Bb = Bs + buf * 32 * 68;
        #pragma unroll
        for (int ks = 0; ks < 4; ks++) {
            const int kk = ks * 8;
            uint32_t a[4][4], bf[4][2];
            #pragma unroll
            for (int mt = 0; mt < 4; mt++) {
                int mr = wm + mt * 16;
                a[mt][0] = ldtf(Ab + (mr + g) * 36 + kk + tg);
                a[mt][1] = ldtf(Ab + (mr + g + 8) * 36 + kk + tg);
                a[mt][2] = ldtf(Ab + (mr + g) * 36 + kk + tg + 4);
                a[mt][3] = ldtf(Ab + (mr + g + 8) * 36 + kk + tg + 4);
            }
            #pragma unroll
            for (int nt = 0; nt < 4; nt++) {
                int nc = wn + nt * 8 + g;
                bf[nt][0] = ldtf(Bb + (kk + tg) * 68 + nc);
                bf[nt][1] = ldtf(Bb + (kk + tg + 4) * 68 + nc);
            }
            #pragma unroll
            for (int mt = 0; mt < 4; mt++)
                #pragma unroll
                for (int nt = 0; nt < 4; nt++)
                    mma_tf32(acc[mt][nt], a[mt][0], a[mt][1], a[mt][2], a[mt][3],
                             bf[nt][0], bf[nt][1]);
        }
    }

    #pragma unroll
    for (int mt = 0; mt < 4; mt++) {
        #pragma unroll
        for (int nt = 0; nt < 4; nt++) {
            int n0 = bn + wn + nt * 8 + tg * 2;
            float b0v = bias[n0], b1v = bias[n0 + 1];
            int r0 = bm + wm + mt * 16 + g;
            C[(size_t)r0 * N + n0]           = acc[mt][nt][0] + b0v;
            C[(size_t)r0 * N + n0 + 1]       = acc[mt][nt][1] + b1v;
            C[(size_t)(r0 + 8) * N + n0]     = acc[mt][nt][2] + b0v;
            C[(size_t)(r0 + 8) * N + n0 + 1] = acc[mt][nt][3] + b1v;
        }
    }
}

// ---------------------------------------------------------------------------
// Scores (R4 mainloop): E[b,h,t,s] = exp((Q.K)/8 + mask), kpm==0 -> 0.
// Also emits per-row partial sums over this block's 128 columns.
// Block 128(t) x 128(s), 8 warps (2x4), single-shot K=64, raw-fp32 smem.
// ---------------------------------------------------------------------------
__global__ __launch_bounds__(256, 2) void score_tc(
    const float* __restrict__ Q, const float* __restrict__ Kp,
    const float* __restrict__ attn_mask, const int* __restrict__ kpm,
    float* __restrict__ attn, float* __restrict__ psum)
{
    extern __shared__ float dsm[];
    float* Qs = dsm;              // [128][68]
    float* Ks = dsm + 128 * 68;   // [128][68]  (n-major: [s][d])
    __shared__ float row_sum[128][4];
    const uint32_t qbase = (uint32_t)__cvta_generic_to_shared(Qs);
    const uint32_t kbase = (uint32_t)__cvta_generic_to_shared(Ks);

    const int tid = threadIdx.x;
    const int wid = tid >> 5, lane = tid & 31;
    const int g = lane >> 2, tg = lane & 3;
    const int bh = blockIdx.z;
    const int b = bh >> 3, h = bh & 7;
    const int t0 = blockIdx.y * 128, s0 = blockIdx.x * 128;
    const int wm = (wid >> 2) * 64, wn = (wid & 3) * 32;

    #pragma unroll
    for (int i = tid; i < 128 * 16; i += 256) {
        int r = i >> 4, seg = i & 15;
        cp_async16(qbase + (r * 68 + seg * 4) * 4,
                   Q + (size_t)(b * T_ + t0 + r) * DQ_ + h * HD_ + seg * 4);
        cp_async16(kbase + (r * 68 + seg * 4) * 4,
                   Kp + (size_t)(b * S_ + s0 + r) * DQ_ + h * HD_ + seg * 4);
    }
    cp_commit();
    cp_wait0();
    __syncthreads();

    float acc[4][4][4];
    #pragma unroll
    for (int mt = 0; mt < 4; mt++)
        #pragma unroll
        for (int nt = 0; nt < 4; nt++)
            #pragma unroll
            for (int r = 0; r < 4; r++) acc[mt][nt][r] = 0.f;

    #pragma unroll
    for (int ks = 0; ks < 8; ks++) {
        const int kk = ks * 8;
        uint32_t a[4][4], bf[4][2];
        #pragma unroll
        for (int mt = 0; mt < 4; mt++) {
            int mr = wm + mt * 16;
            a[mt][0] = ldtf(Qs + (mr + g) * 68 + kk + tg);
            a[mt][1] = ldtf(Qs + (mr + g + 8) * 68 + kk + tg);
            a[mt][2] = ldtf(Qs + (mr + g) * 68 + kk + tg + 4);
            a[mt][3] = ldtf(Qs + (mr + g + 8) * 68 + kk + tg + 4);
        }
        #pragma unroll
        for (int nt = 0; nt < 4; nt++) {
            int nc = wn + nt * 8 + g;
            bf[nt][0] = ldtf(Ks + nc * 68 + kk + tg);
            bf[nt][1] = ldtf(Ks + nc * 68 + kk + tg + 4);
        }
        #pragma unroll
        for (int mt = 0; mt < 4; mt++)
            #pragma unroll
            for (int nt = 0; nt < 4; nt++)
                mma_tf32(acc[mt][nt], a[mt][0], a[mt][1], a[mt][2], a[mt][3],
                         bf[nt][0], bf[nt][1]);
    }

    // kpm per owned column pair (hoisted)
    int kp0[4], kp1[4];
    #pragma unroll
    for (int nt = 0; nt < 4; nt++) {
        int s = s0 + wn + nt * 8 + tg * 2;
        kp0[nt] = kpm[b * S_ + s];
        kp1[nt] = kpm[b * S_ + s + 1];
    }

    // Epilogue: scale + mask -> exp -> write E, accumulate row partial sums.
    #pragma unroll
    for (int mt = 0; mt < 4; mt++) {
        #pragma unroll
        for (int half = 0; half < 2; half++) {
            int rloc = wm + mt * 16 + half * 8 + g;
            int tr = t0 + rloc;
            float s_loc = 0.f;
            #pragma unroll
            for (int nt = 0; nt < 4; nt++) {
                int s = s0 + wn + nt * 8 + tg * 2;
                float v0 = acc[mt][nt][half * 2]     * 0.125f + attn_mask[(size_t)tr * S_ + s];
                float v1 = acc[mt][nt][half * 2 + 1] * 0.125f + attn_mask[(size_t)tr * S_ + s + 1];
                float E0 = (kp0[nt] == 0) ? 0.f : __expf(v0);
                float E1 = (kp1[nt] == 0) ? 0.f : __expf(v1);
                attn[((size_t)bh * T_ + tr) * S_ + s]     = E0;
                attn[((size_t)bh * T_ + tr) * S_ + s + 1] = E1;
                s_loc += E0 + E1;
            }
            // reduce over tg (lanes differing in bits 0-1)
            s_loc += __shfl_xor_sync(0xffffffffu, s_loc, 1);
            s_loc += __shfl_xor_sync(0xffffffffu, s_loc, 2);
            if (tg == 0) row_sum[rloc][wid & 3] = s_loc;
        }
    }
    __syncthreads();
    if (tid < 128) {
        float S = row_sum[tid][0] + row_sum[tid][1] + row_sum[tid][2] + row_sum[tid][3];
        psum[((size_t)bh * T_ + t0 + tid) * NSB + blockIdx.x] = S;
    }
}

// ---------------------------------------------------------------------------
// Combine partial sums: inv[row] = 1 / sum_i psum[row][i]
// ---------------------------------------------------------------------------
__global__ __launch_bounds__(256) void combine_inv(
    const float* __restrict__ psum, float* __restrict__ inv)
{
    int row = blockIdx.x * 256 + threadIdx.x;
    float s = 0.f;
    #pragma unroll
    for (int i = 0; i < NSB; i++) s += psum[(size_t)row * NSB + i];
    inv[row] = 1.0f / s;
}

// ---------------------------------------------------------------------------
// AV + normalize: for each stage, p = E * inv[row]; write p to attn (d_out);
// store tf32(p) in-place in smem; MMA ctx += p @ V.
// Block 128(t) x 64(d), 4 warps (2x2), BK=32 over S, cp.async double-buffered.
// ---------------------------------------------------------------------------
__global__ __launch_bounds__(128, 4) void av_tc(
    float* __restrict__ attn, const float* __restrict__ Vp,
    const float* __restrict__ inv, float* __restrict__ ctx)
{
    extern __shared__ float dsm[];
    float* As = dsm;                    // [2][128][36]
    float* Bs = dsm + 2 * 128 * 36;     // [2][32][68]
    __shared__ float inv_s[128];
    const uint32_t abase = (uint32_t)__cvta_generic_to_shared(As);
    const uint32_t bbase = (uint32_t)__cvta_generic_to_shared(Bs);

    const int tid = threadIdx.x;
    const int wid = tid >> 5, lane = tid & 31;
    const int g = lane >> 2, tg = lane & 3;
    const int bh = blockIdx.y;
    const int b = bh >> 3, h = bh & 7;
    const int t0 = blockIdx.x * 128;
    const int wm = (wid >> 1) * 64, wn = (wid & 1) * 32;

    float* arow = attn + ((size_t)bh * T_ + t0) * S_;

    if (tid < 128) inv_s[tid] = inv[(size_t)bh * T_ + t0 + tid];

    float acc[4][4][4];
    #pragma unroll
    for (int mt = 0; mt < 4; mt++)
        #pragma unroll
        for (int nt = 0; nt < 4; nt++)
            #pragma unroll
            for (int r = 0; r < 4; r++) acc[mt][nt][r] = 0.f;

    auto load_stage = [&](int buf, int k0) {
        uint32_t ab = abase + (uint32_t)buf * 128 * 36 * 4;
        #pragma unroll
        for (int i = tid; i < 128 * 8; i += 128) {
            int r = i >> 3, seg = i & 7;
            cp_async16(ab + (r * 36 + seg * 4) * 4,
                       arow + (size_t)r * S_ + k0 + seg * 4);
        }
        uint32_t bb = bbase + (uint32_t)buf * 32 * 68 * 4;
        #pragma unroll
        for (int i = tid; i < 32 * 16; i += 128) {
            int r = i >> 4, seg = i & 15;
            cp_async16(bb + (r * 68 + seg * 4) * 4,
                       Vp + (size_t)(b * S_ + k0 + r) * DQ_ + h * HD_ + seg * 4);
        }
        cp_commit();
    };

    load_stage(0, 0);
    int buf = 0;
    for (int k0 = 0; k0 < S_; k0 += 32, buf ^= 1) {
        cp_wait0();
        __syncthreads();
        if (k0 + 32 < S_) load_stage(buf ^ 1, k0 + 32);

        float* Ab = As + buf * 128 * 36;
        const float* Bb = Bs + buf * 32 * 68;

        // Normalize pass: p = E * inv; write attn; store tf32 bits in place.
        {
            const int c = lane, rr = wid;   // rr = 0..3
            #pragma unroll
            for (int j = 0; j < 32; j++) {
                int r = j * 4 + rr;
                float p = Ab[r * 36 + c] * inv_s[r];
                arow[(size_t)r * S_ + k0 + c] = p;
                ((uint32_t*)Ab)[r * 36 + c] = f2tf32(p);
            }
        }
        __syncthreads();

        #pragma unroll
        for (int ks = 0; ks < 4; ks++) {
            const int kk = ks * 8;
            uint32_t a[4][4], bf[4][2];
            #pragma unroll
            for (int mt = 0; mt < 4; mt++) {
                int mr = wm + mt * 16;
                a[mt][0] = ((const uint32_t*)Ab)[(mr + g) * 36 + kk + tg];
                a[mt][1] = ((const uint32_t*)Ab)[(mr + g + 8) * 36 + kk + tg];
                a[mt][2] = ((const uint32_t*)Ab)[(mr + g) * 36 + kk + tg + 4];
                a[mt][3] = ((const uint32_t*)Ab)[(mr + g + 8) * 36 + kk + tg + 4];
            }
            #pragma unroll
            for (int nt = 0; nt < 4; nt++) {
                int nc = wn + nt * 8 + g;
                bf[nt][0] = ldtf(Bb + (kk + tg) * 68 + nc);
                bf[nt][1] = ldtf(Bb + (kk + tg + 4) * 68 + nc);
            }
            #pragma unroll
            for (int mt = 0; mt < 4; mt++)
                #pragma unroll
                for (int nt = 0; nt < 4; nt++)
                    mma_tf32(acc[mt][nt], a[mt][0], a[mt][1], a[mt][2], a[mt][3],
                             bf[nt][0], bf[nt][1]);
        }
        __syncthreads();
    }

    #pragma unroll
    for (int mt = 0; mt < 4; mt++) {
        #pragma unroll
        for (int nt = 0; nt < 4; nt++) {
            int d0 = wn + nt * 8 + tg * 2;
            int t = t0 + wm + mt * 16 + g;
            ctx[(size_t)(b * T_ + t) * DQ_ + h * HD_ + d0]         = acc[mt][nt][0];
            ctx[(size_t)(b * T_ + t) * DQ_ + h * HD_ + d0 + 1]     = acc[mt][nt][1];
            ctx[(size_t)(b * T_ + t + 8) * DQ_ + h * HD_ + d0]     = acc[mt][nt][2];
            ctx[(size_t)(b * T_ + t + 8) * DQ_ + h * HD_ + d0 + 1] = acc[mt][nt][3];
        }
    }
}

// ---------------------------------------------------------------------------
// Launch (single stream)
// ---------------------------------------------------------------------------
extern "C" void kernel_launch(void* const* d_in, const int* in_sizes, int n_in,
                              void* d_out, int out_size)
{
    const float* query     = (const float*)d_in[0];
    const float* key       = (const float*)d_in[1];
    const float* value     = (const float*)d_in[2];
    const int*   kpm       = (const int*)  d_in[3];
    const float* attn_mask = (const float*)d_in[4];
    const float* Wq = (const float*)d_in[5];
    const float* bq = (const float*)d_in[6];
    const float* Wk = (const float*)d_in[7];
    const float* bk = (const float*)d_in[8];
    const float* Wv = (const float*)d_in[9];
    const float* bv = (const float*)d_in[10];
    const float* Wo = (const float*)d_in[11];
    const float* bo = (const float*)d_in[12];

    float* out  = (float*)d_out;                        // [B,T,DQ]
    float* attn = out + (size_t)B_ * T_ * DQ_;          // [B,H,T,S]

    float *Qp, *Kp, *Vp, *Cp, *Ps, *Iv;
    cudaGetSymbolAddress((void**)&Qp, g_Q);
    cudaGetSymbolAddress((void**)&Kp, g_K);
    cudaGetSymbolAddress((void**)&Vp, g_V);
    cudaGetSymbolAddress((void**)&Cp, g_ctx);
    cudaGetSymbolAddress((void**)&Ps, g_psum);
    cudaGetSymbolAddress((void**)&Iv, g_inv);

    const int GEMM_SMEM  = (2 * 128 * 36 + 2 * 32 * 68) * 4;   // 54272
    const int SCORE_SMEM = (2 * 128 * 68) * 4;                  // 69632

    static int attr_done = 0;
    if (!attr_done) {
        cudaFuncSetAttribute(gemm_bias_tc, cudaFuncAttributeMaxDynamicSharedMemorySize, GEMM_SMEM);
        cudaFuncSetAttribute(score_tc,     cudaFuncAttributeMaxDynamicSharedMemorySize, SCORE_SMEM);
        cudaFuncSetAttribute(av_tc,        cudaFuncAttributeMaxDynamicSharedMemorySize, GEMM_SMEM);
        attr_done = 1;
    }

    const int M = B_ * T_;   // 8192

    // Projections (tf32 tensor cores, cp.async pipelined)
    gemm_bias_tc<<<dim3(DQ_ / 64, M / 128), 128, GEMM_SMEM>>>(query, Wq, bq, Qp, M, DQ_, DQ_);
    gemm_bias_tc<<<dim3(DQ_ / 64, M / 128), 128, GEMM_SMEM>>>(key,   Wk, bk, Kp, M, DQ_, DKV_);
    gemm_bias_tc<<<dim3(DQ_ / 64, M / 128), 128, GEMM_SMEM>>>(value, Wv, bv, Vp, M, DQ_, DKV_);

    // E = exp(scores) + per-row partial sums -> attn region of d_out
    score_tc<<<dim3(S_ / 128, T_ / 128, B_ * H_), 256, SCORE_SMEM>>>(Qp, Kp, attn_mask, kpm, attn, Ps);

    // inv[row] = 1 / sum
    combine_inv<<<(B_ * H_ * T_) / 256, 256>>>(Ps, Iv);

    // normalize + write attn + ctx = attn @ V
    av_tc<<<dim3(T_ / 128, B_ * H_), 128, GEMM_SMEM>>>(attn, Vp, Iv, Cp);

    // Output projection
    gemm_bias_tc<<<dim3(DQ_ / 64, M / 128), 128, GEMM_SMEM>>>(Cp, Wo, bo, out, M, DQ_, DQ_);
}

// round 11
// speedup vs baseline: 1.1578x; 1.1286x over previous
#include <cuda_runtime.h>
#include <cuda_fp16.h>
#include <math.h>
#include <stdint.h>

// Problem constants
#define B_   4
#define T_   2048
#define S_   2048
#define DQ_  512
#define DKV_ 1024
#define H_   8
#define HD_  64

// Scratch buffers (allocation-free: __device__ globals)
__device__ __half g_Qh[B_ * T_ * DQ_];            // [B,T,512] half (h*64+d inside)
__device__ __half g_Kh[B_ * S_ * DQ_];            // [B,S,512] half
__device__ __half g_Vt[B_ * H_ * HD_ * (size_t)S_]; // V transposed: [b,h,d,s] half
__device__ float  g_ctx[B_ * T_ * DQ_];

// ---------------------------------------------------------------------------
// Helpers
// ---------------------------------------------------------------------------
__device__ __forceinline__ uint32_t f2tf32(float f) {
    uint32_t r;
    asm("cvt.rna.tf32.f32 %0, %1;" : "=r"(r) : "f"(f));
    return r;
}
__device__ __forceinline__ uint32_t ldtf(const float* p) { return f2tf32(*p); }

// pack two fp32 -> f16x2 (lo = first k element, hi = second)
__device__ __forceinline__ uint32_t pack_h2(float lo, float hi) {
    uint32_t r;
    asm("cvt.rn.f16x2.f32 %0, %1, %2;" : "=r"(r) : "f"(hi), "f"(lo));
    return r;
}

__device__ __forceinline__ void mma_tf32(float d[4],
                                         uint32_t a0, uint32_t a1, uint32_t a2, uint32_t a3,
                                         uint32_t b0, uint32_t b1) {
    asm volatile(
        "mma.sync.aligned.m16n8k8.row.col.f32.tf32.tf32.f32 "
        "{%0,%1,%2,%3}, {%4,%5,%6,%7}, {%8,%9}, {%0,%1,%2,%3};\n"
        : "+f"(d[0]), "+f"(d[1]), "+f"(d[2]), "+f"(d[3])
        : "r"(a0), "r"(a1), "r"(a2), "r"(a3), "r"(b0), "r"(b1));
}

__device__ __forceinline__ void mma_f16(float d[4],
                                        uint32_t a0, uint32_t a1, uint32_t a2, uint32_t a3,
                                        uint32_t b0, uint32_t b1) {
    asm volatile(
        "mma.sync.aligned.m16n8k16.row.col.f32.f16.f16.f32 "
        "{%0,%1,%2,%3}, {%4,%5,%6,%7}, {%8,%9}, {%0,%1,%2,%3};\n"
        : "+f"(d[0]), "+f"(d[1]), "+f"(d[2]), "+f"(d[3])
        : "r"(a0), "r"(a1), "r"(a2), "r"(a3), "r"(b0), "r"(b1));
}

__device__ __forceinline__ void cp_async16(uint32_t s, const void* g) {
    asm volatile("cp.async.cg.shared.global [%0], [%1], 16;\n" :: "r"(s), "l"(g));
}
__device__ __forceinline__ void cp_commit() { asm volatile("cp.async.commit_group;\n" ::: "memory"); }
__device__ __forceinline__ void cp_wait0()  { asm volatile("cp.async.wait_group 0;\n" ::: "memory"); }

// ---------------------------------------------------------------------------
// Projections:  C[M,N] = A[M,K] @ W[K,N] + bias[N]   (tf32 mainloop, proven)
// MODE 0: fp32 out (O-proj). MODE 1: half out, normal layout (Q,K).
// MODE 2: half out, transposed-V layout g_Vt[b,h,d,t].
// ---------------------------------------------------------------------------
template <int MODE>
__global__ __launch_bounds__(128, 4) void gemm_bias_tc(
    const float* __restrict__ A, const float* __restrict__ W,
    const float* __restrict__ bias, void* __restrict__ Cout,
    int M, int N, int K)
{
    extern __shared__ float dsm[];
    float* As = dsm;                    // [2][128][36]
    float* Bs = dsm + 2 * 128 * 36;     // [2][32][68]
    const uint32_t abase = (uint32_t)__cvta_generic_to_shared(As);
    const uint32_t bbase = (uint32_t)__cvta_generic_to_shared(Bs);

    const int tid = threadIdx.x;
    const int wid = tid >> 5, lane = tid & 31;
    const int g = lane >> 2, tg = lane & 3;
    const int bm = blockIdx.y * 128, bn = blockIdx.x * 64;
    const int wm = (wid >> 1) * 64, wn = (wid & 1) * 32;

    float acc[4][4][4];
    #pragma unroll
    for (int mt = 0; mt < 4; mt++)
        #pragma unroll
        for (int nt = 0; nt < 4; nt++)
            #pragma unroll
            for (int r = 0; r < 4; r++) acc[mt][nt][r] = 0.f;

    auto load_stage = [&](int buf, int k0) {
        uint32_t ab = abase + (uint32_t)buf * 128 * 36 * 4;
        #pragma unroll
        for (int i = tid; i < 128 * 8; i += 128) {
            int r = i >> 3, seg = i & 7;
            cp_async16(ab + (r * 36 + seg * 4) * 4,
                       A + (size_t)(bm + r) * K + k0 + seg * 4);
        }
        uint32_t bb = bbase + (uint32_t)buf * 32 * 68 * 4;
        #pragma unroll
        for (int i = tid; i < 32 * 16; i += 128) {
            int r = i >> 4, seg = i & 15;
            cp_async16(bb + (r * 68 + seg * 4) * 4,
                       W + (size_t)(k0 + r) * N + bn + seg * 4);
        }
        cp_commit();
    };

    load_stage(0, 0);
    int buf = 0;
    for (int k0 = 0; k0 < K; k0 += 32, buf ^= 1) {
        cp_wait0();
        __syncthreads();
        if (k0 + 32 < K) load_stage(buf ^ 1, k0 + 32);

        const float* Ab = As + buf * 128 * 36;
        const float* Bb = Bs + buf * 32 * 68;
        #pragma unroll
        for (int ks = 0; ks < 4; ks++) {
            const int kk = ks * 8;
            uint32_t a[4][4], bf[4][2];
            #pragma unroll
            for (int mt = 0; mt < 4; mt++) {
                int mr = wm + mt * 16;
                a[mt][0] = ldtf(Ab + (mr + g) * 36 + kk + tg);
                a[mt][1] = ldtf(Ab + (mr + g + 8) * 36 + kk + tg);
                a[mt][2] = ldtf(Ab + (mr + g) * 36 + kk + tg + 4);
                a[mt][3] = ldtf(Ab + (mr + g + 8) * 36 + kk + tg + 4);
            }
            #pragma unroll
            for (int nt = 0; nt < 4; nt++) {
                int nc = wn + nt * 8 + g;
                bf[nt][0] = ldtf(Bb + (kk + tg) * 68 + nc);
                bf[nt][1] = ldtf(Bb + (kk + tg + 4) * 68 + nc);
            }
            #pragma unroll
            for (int mt = 0; mt < 4; mt++)
                #pragma unroll
                for (int nt = 0; nt < 4; nt++)
                    mma_tf32(acc[mt][nt], a[mt][0], a[mt][1], a[mt][2], a[mt][3],
                             bf[nt][0], bf[nt][1]);
        }
    }

    #pragma unroll
    for (int mt = 0; mt < 4; mt++) {
        #pragma unroll
        for (int nt = 0; nt < 4; nt++) {
            int n0 = bn + wn + nt * 8 + tg * 2;
            float b0v = bias[n0], b1v = bias[n0 + 1];
            int r0 = bm + wm + mt * 16 + g;
            float v00 = acc[mt][nt][0] + b0v, v01 = acc[mt][nt][1] + b1v;
            float v10 = acc[mt][nt][2] + b0v, v11 = acc[mt][nt][3] + b1v;
            if (MODE == 0) {
                float* C = (float*)Cout;
                C[(size_t)r0 * N + n0]           = v00;
                C[(size_t)r0 * N + n0 + 1]       = v01;
                C[(size_t)(r0 + 8) * N + n0]     = v10;
                C[(size_t)(r0 + 8) * N + n0 + 1] = v11;
            } else if (MODE == 1) {
                __half* C = (__half*)Cout;
                C[(size_t)r0 * N + n0]           = __float2half(v00);
                C[(size_t)r0 * N + n0 + 1]       = __float2half(v01);
                C[(size_t)(r0 + 8) * N + n0]     = __float2half(v10);
                C[(size_t)(r0 + 8) * N + n0 + 1] = __float2half(v11);
            } else {
                // transposed V: Vt[((b*8+h)*64+d)*2048 + t]
                __half* C = (__half*)Cout;
                int h0 = n0 >> 6, d0 = n0 & 63;
                int b0i = r0 >> 11, t0i = r0 & 2047;
                size_t base0 = ((size_t)(b0i * 8 + h0) * 64 + d0) * 2048;
                C[base0 + t0i]            = __float2half(v00);
                C[base0 + 2048 + t0i]     = __float2half(v01);   // d0+1 (same h: n0 even)
                C[base0 + t0i + 8]        = __float2half(v10);   // r0+8 -> t+8 (same b: 128-tile inside T)
                C[base0 + 2048 + t0i + 8] = __float2half(v11);
            }
        }
    }
}

// ---------------------------------------------------------------------------
// Scores (fp16 mma): attn[b,h,t,s] = (Q.K)/8 + mask, kpm==0 -> -inf
// Block 128(t) x 128(s), 8 warps (2x4), single-shot K=64.
// Q/K tiles are HALF, stride 72 halves (144B): words/row = 36 == 4 mod 32 ->
// fragment LDS.32 pattern (4g+tg) covers 32 distinct banks. Zero cvt in loop.
// ---------------------------------------------------------------------------
__global__ __launch_bounds__(256, 2) void score_h(
    const __half* __restrict__ Q, const __half* __restrict__ Kp,
    const float* __restrict__ attn_mask, const int* __restrict__ kpm,
    float* __restrict__ attn)
{
    __shared__ __half Qs[128 * 72];
    __shared__ __half Ks[128 * 72];
    const uint32_t qbase = (uint32_t)__cvta_generic_to_shared(Qs);
    const uint32_t kbase = (uint32_t)__cvta_generic_to_shared(Ks);

    const int tid = threadIdx.x;
    const int wid = tid >> 5, lane = tid & 31;
    const int g = lane >> 2, tg = lane & 3;
    const int bh = blockIdx.z;
    const int b = bh >> 3, h = bh & 7;
    const int t0 = blockIdx.y * 128, s0 = blockIdx.x * 128;
    const int wm = (wid >> 2) * 64, wn = (wid & 3) * 32;

    // Load Q,K tiles: 128 rows x 128B (64 halves) = 8 segs of 16B each.
    #pragma unroll
    for (int i = tid; i < 128 * 8; i += 256) {
        int r = i >> 3, seg = i & 7;
        cp_async16(qbase + (r * 72 + seg * 8) * 2,
                   Q + (size_t)(b * T_ + t0 + r) * DQ_ + h * HD_ + seg * 8);
        cp_async16(kbase + (r * 72 + seg * 8) * 2,
                   Kp + (size_t)(b * S_ + s0 + r) * DQ_ + h * HD_ + seg * 8);
    }
    cp_commit();
    cp_wait0();
    __syncthreads();

    float acc[4][4][4];
    #pragma unroll
    for (int mt = 0; mt < 4; mt++)
        #pragma unroll
        for (int nt = 0; nt < 4; nt++)
            #pragma unroll
            for (int r = 0; r < 4; r++) acc[mt][nt][r] = 0.f;

    #pragma unroll
    for (int ks = 0; ks < 4; ks++) {            // K=64 in 4 k16 steps
        const int kk = ks * 16;
        uint32_t a[4][4], bf[4][2];
        #pragma unroll
        for (int mt = 0; mt < 4; mt++) {
            int mr = wm + mt * 16;
            a[mt][0] = *(const uint32_t*)(Qs + (mr + g) * 72 + kk + 2 * tg);
            a[mt][1] = *(const uint32_t*)(Qs + (mr + g + 8) * 72 + kk + 2 * tg);
            a[mt][2] = *(const uint32_t*)(Qs + (mr + g) * 72 + kk + 8 + 2 * tg);
            a[mt][3] = *(const uint32_t*)(Qs + (mr + g + 8) * 72 + kk + 8 + 2 * tg);
        }
        #pragma unroll
        for (int nt = 0; nt < 4; nt++) {
            int nc = wn + nt * 8 + g;
            bf[nt][0] = *(const uint32_t*)(Ks + nc * 72 + kk + 2 * tg);
            bf[nt][1] = *(const uint32_t*)(Ks + nc * 72 + kk + 8 + 2 * tg);
        }
        #pragma unroll
        for (int mt = 0; mt < 4; mt++)
            #pragma unroll
            for (int nt = 0; nt < 4; nt++)
                mma_f16(acc[mt][nt], a[mt][0], a[mt][1], a[mt][2], a[mt][3],
                        bf[nt][0], bf[nt][1]);
    }

    // Epilogue: scale + mask + kpm (raw masked scores; softmax kernel follows)
    #pragma unroll
    for (int mt = 0; mt < 4; mt++) {
        #pragma unroll
        for (int nt = 0; nt < 4; nt++) {
            int s = s0 + wn + nt * 8 + tg * 2;
            int kp0 = kpm[b * S_ + s], kp1 = kpm[b * S_ + s + 1];
            int t = t0 + wm + mt * 16 + g;
            #pragma unroll
            for (int half = 0; half < 2; half++) {
                int tr = t + half * 8;
                float v0 = acc[mt][nt][half * 2]     * 0.125f + attn_mask[(size_t)tr * S_ + s];
                float v1 = acc[mt][nt][half * 2 + 1] * 0.125f + attn_mask[(size_t)tr * S_ + s + 1];
                if (kp0 == 0) v0 = -INFINITY;
                if (kp1 == 0) v1 = -INFINITY;
                attn[((size_t)bh * T_ + tr) * S_ + s]     = v0;
                attn[((size_t)bh * T_ + tr) * S_ + s + 1] = v1;
            }
        }
    }
}

// ---------------------------------------------------------------------------
// In-place row softmax over S=2048 (R4, proven).
// ---------------------------------------------------------------------------
__global__ __launch_bounds__(256) void softmax_kernel(float* __restrict__ attn)
{
    size_t row = blockIdx.x;
    float* p = attn + row * (size_t)S_;
    int tid = threadIdx.x;

    float v[8];
    #pragma unroll
    for (int i = 0; i < 8; i++) v[i] = p[tid + 256 * i];

    float m = v[0];
    #pragma unroll
    for (int i = 1; i < 8; i++) m = fmaxf(m, v[i]);
    #pragma unroll
    for (int o = 16; o > 0; o >>= 1) m = fmaxf(m, __shfl_xor_sync(0xffffffffu, m, o));

    __shared__ float red[8];
    if ((tid & 31) == 0) red[tid >> 5] = m;
    __syncthreads();
    if (tid < 32) {
        float x = (tid < 8) ? red[tid] : -INFINITY;
        #pragma unroll
        for (int o = 4; o > 0; o >>= 1) x = fmaxf(x, __shfl_xor_sync(0xffffffffu, x, o));
        if (tid == 0) red[0] = x;
    }
    __syncthreads();
    m = red[0];
    __syncthreads();

    float s = 0.f;
    #pragma unroll
    for (int i = 0; i < 8; i++) { v[i] = __expf(v[i] - m); s += v[i]; }
    #pragma unroll
    for (int o = 16; o > 0; o >>= 1) s += __shfl_xor_sync(0xffffffffu, s, o);
    if ((tid & 31) == 0) red[tid >> 5] = s;
    __syncthreads();
    if (tid < 32) {
        float x = (tid < 8) ? red[tid] : 0.f;
        #pragma unroll
        for (int o = 4; o > 0; o >>= 1) x += __shfl_xor_sync(0xffffffffu, x, o);
        if (tid == 0) red[0] = x;
    }
    __syncthreads();
    float inv = 1.0f / red[0];

    #pragma unroll
    for (int i = 0; i < 8; i++) p[tid + 256 * i] = v[i] * inv;
}

// ---------------------------------------------------------------------------
// AV (fp16 mma): ctx[b,t,h,:] = attn[b,h,t,:] @ V[b,:,h,:]
// attn fp32 staged [2][128][40] (stride 40 words: 8g+2tg distinct per phase ->
// conflict-free LDS.64); Vt half [2][64][40] (stride 40 halves = 20 words:
// 20g+tg distinct mod 32 -> conflict-free LDS.32). A frags packed via f16x2 cvt.
// ---------------------------------------------------------------------------
__global__ __launch_bounds__(128, 4) void av_h(
    const float* __restrict__ attn, const __half* __restrict__ Vt,
    float* __restrict__ ctx)
{
    extern __shared__ float dsm[];
    float* As = dsm;                                   // [2][128][40] fp32
    __half* Vs = (__half*)(dsm + 2 * 128 * 40);        // [2][64][40] half
    const uint32_t abase = (uint32_t)__cvta_generic_to_shared(As);
    const uint32_t vbase = (uint32_t)__cvta_generic_to_shared(Vs);

    const int tid = threadIdx.x;
    const int wid = tid >> 5, lane = tid & 31;
    const int g = lane >> 2, tg = lane & 3;
    const int bh = blockIdx.y;
    const int t0 = blockIdx.x * 128;
    const int wm = (wid >> 1) * 64, wn = (wid & 1) * 32;

    const float* arow = attn + ((size_t)bh * T_ + t0) * S_;
    const __half* vrow = Vt + (size_t)bh * HD_ * S_;   // [64][2048] half

    float acc[4][4][4];
    #pragma unroll
    for (int mt = 0; mt < 4; mt++)
        #pragma unroll
        for (int nt = 0; nt < 4; nt++)
            #pragma unroll
            for (int r = 0; r < 4; r++) acc[mt][nt][r] = 0.f;

    auto load_stage = [&](int buf, int k0) {
        uint32_t ab = abase + (uint32_t)buf * 128 * 40 * 4;
        #pragma unroll
        for (int i = tid; i < 128 * 8; i += 128) {     // attn: 128 rows x 128B
            int r = i >> 3, seg = i & 7;
            cp_async16(ab + (r * 40 + seg * 4) * 4,
                       arow + (size_t)r * S_ + k0 + seg * 4);
        }
        uint32_t vb = vbase + (uint32_t)buf * 64 * 40 * 2;
        #pragma unroll
        for (int i = tid; i < 64 * 4; i += 128) {      // Vt: 64 d-rows x 64B (32 halves)
            int r = i >> 2, seg = i & 3;
            cp_async16(vb + (r * 40 + seg * 8) * 2,
                       vrow + (size_t)r * S_ + k0 + seg * 8);
        }
        cp_commit();
    };

    load_stage(0, 0);
    int buf = 0;
    for (int k0 = 0; k0 < S_; k0 += 32, buf ^= 1) {
        cp_wait0();
        __syncthreads();
        if (k0 + 32 < S_) load_stage(buf ^ 1, k0 + 32);

        const float* Ab = As + buf * 128 * 40;
        const __half* Vb = Vs + buf * 64 * 40;
        #pragma unroll
        for (int ks = 0; ks < 2; ks++) {               // 2 k16 steps per BK=32
            const int kk = ks * 16;
            uint32_t a[4][4], bf[4][2];
            #pragma unroll
            for (int mt = 0; mt < 4; mt++) {
                int mr = wm + mt * 16;
                float2 p0 = *(const float2*)(Ab + (mr + g) * 40 + kk + 2 * tg);
                float2 p1 = *(const float2*)(Ab + (mr + g + 8) * 40 + kk + 2 * tg);
                float2 p2 = *(const float2*)(Ab + (mr + g) * 40 + kk + 8 + 2 * tg);
                float2 p3 = *(const float2*)(Ab + (mr + g + 8) * 40 + kk + 8 + 2 * tg);
                a[mt][0] = pack_h2(p0.x, p0.y);
                a[mt][1] = pack_h2(p1.x, p1.y);
                a[mt][2] = pack_h2(p2.x, p2.y);
                a[mt][3] = pack_h2(p3.x, p3.y);
            }
            #pragma unroll
            for (int nt = 0; nt < 4; nt++) {
                int nc = wn + nt * 8 + g;
                bf[nt][0] = *(const uint32_t*)(Vb + nc * 40 + kk + 2 * tg);
                bf[nt][1] = *(const uint32_t*)(Vb + nc * 40 + kk + 8 + 2 * tg);
            }
            #pragma unroll
            for (int mt = 0; mt < 4; mt++)
                #pragma unroll
                for (int nt = 0; nt < 4; nt++)
                    mma_f16(acc[mt][nt], a[mt][0], a[mt][1], a[mt][2], a[mt][3],
                            bf[nt][0], bf[nt][1]);
        }
        __syncthreads();
    }

    const int b = bh >> 3, h = bh & 7;
    #pragma unroll
    for (int mt = 0; mt < 4; mt++) {
        #pragma unroll
        for (int nt = 0; nt < 4; nt++) {
            int d0 = wn + nt * 8 + tg * 2;
            int t = t0 + wm + mt * 16 + g;
            ctx[(size_t)(b * T_ + t) * DQ_ + h * HD_ + d0]         = acc[mt][nt][0];
            ctx[(size_t)(b * T_ + t) * DQ_ + h * HD_ + d0 + 1]     = acc[mt][nt][1];
            ctx[(size_t)(b * T_ + t + 8) * DQ_ + h * HD_ + d0]     = acc[mt][nt][2];
            ctx[(size_t)(b * T_ + t + 8) * DQ_ + h * HD_ + d0 + 1] = acc[mt][nt][3];
        }
    }
}

// ---------------------------------------------------------------------------
// Launch (single stream)
// ---------------------------------------------------------------------------
extern "C" void kernel_launch(void* const* d_in, const int* in_sizes, int n_in,
                              void* d_out, int out_size)
{
    const float* query     = (const float*)d_in[0];
    const float* key       = (const float*)d_in[1];
    const float* value     = (const float*)d_in[2];
    const int*   kpm       = (const int*)  d_in[3];
    const float* attn_mask = (const float*)d_in[4];
    const float* Wq = (const float*)d_in[5];
    const float* bq = (const float*)d_in[6];
    const float* Wk = (const float*)d_in[7];
    const float* bk = (const float*)d_in[8];
    const float* Wv = (const float*)d_in[9];
    const float* bv = (const float*)d_in[10];
    const float* Wo = (const float*)d_in[11];
    const float* bo = (const float*)d_in[12];

    float* out  = (float*)d_out;                        // [B,T,DQ]
    float* attn = out + (size_t)B_ * T_ * DQ_;          // [B,H,T,S]

    __half *Qh, *Kh, *Vt;
    float *Cp;
    cudaGetSymbolAddress((void**)&Qh, g_Qh);
    cudaGetSymbolAddress((void**)&Kh, g_Kh);
    cudaGetSymbolAddress((void**)&Vt, g_Vt);
    cudaGetSymbolAddress((void**)&Cp, g_ctx);

    const int GEMM_SMEM = (2 * 128 * 36 + 2 * 32 * 68) * 4;   // 54272
    const int AV_SMEM   = 2 * 128 * 40 * 4 + 2 * 64 * 40 * 2; // 51200

    static int attr_done = 0;
    if (!attr_done) {
        cudaFuncSetAttribute(gemm_bias_tc<0>, cudaFuncAttributeMaxDynamicSharedMemorySize, GEMM_SMEM);
        cudaFuncSetAttribute(gemm_bias_tc<1>, cudaFuncAttributeMaxDynamicSharedMemorySize, GEMM_SMEM);
        cudaFuncSetAttribute(gemm_bias_tc<2>, cudaFuncAttributeMaxDynamicSharedMemorySize, GEMM_SMEM);
        cudaFuncSetAttribute(av_h,            cudaFuncAttributeMaxDynamicSharedMemorySize, AV_SMEM);
        attr_done = 1;
    }

    const int M = B_ * T_;   // 8192

    // Projections: Q,K -> half (normal layout); V -> half transposed; tf32 mainloop
    gemm_bias_tc<1><<<dim3(DQ_ / 64, M / 128), 128, GEMM_SMEM>>>(query, Wq, bq, Qh, M, DQ_, DQ_);
    gemm_bias_tc<1><<<dim3(DQ_ / 64, M / 128), 128, GEMM_SMEM>>>(key,   Wk, bk, Kh, M, DQ_, DKV_);
    gemm_bias_tc<2><<<dim3(DQ_ / 64, M / 128), 128, GEMM_SMEM>>>(value, Wv, bv, Vt, M, DQ_, DKV_);

    // Scores + mask -> attn region of d_out (fp16 mma)
    score_h<<<dim3(S_ / 128, T_ / 128, B_ * H_), 256>>>(Qh, Kh, attn_mask, kpm, attn);

    // Row softmax in place
    softmax_kernel<<<B_ * H_ * T_, 256>>>(attn);

    // attn @ V -> ctx (fp16 mma, transposed-V tiles)
    av_h<<<dim3(T_ / 128, B_ * H_), 128, AV_SMEM>>>(attn, Vt, Cp);

    // Output projection (fp32 out)
    gemm_bias_tc<0><<<dim3(DQ_ / 64, M / 128), 128, GEMM_SMEM>>>(Cp, Wo, bo, out, M, DQ_, DQ_);
}

// round 12
// speedup vs baseline: 1.4031x; 1.2119x over previous
#include <cuda_runtime.h>
#include <cuda_fp16.h>
#include <math.h>
#include <stdint.h>

// Problem constants
#define B_   4
#define T_   2048
#define S_   2048
#define DQ_  512
#define DKV_ 1024
#define H_   8
#define HD_  64

// Scratch buffers (allocation-free: __device__ globals)
__device__ __half g_Qh[B_ * T_ * DQ_];              // [B,T,512] half
__device__ __half g_Kh[B_ * S_ * DQ_];              // [B,S,512] half
__device__ __half g_Vt[B_ * H_ * HD_ * (size_t)S_]; // V transposed: [b,h,d,s] half
__device__ float  g_ctx[B_ * T_ * DQ_];

// ---------------------------------------------------------------------------
// Helpers
// ---------------------------------------------------------------------------
__device__ __forceinline__ uint32_t f2tf32(float f) {
    uint32_t r;
    asm("cvt.rna.tf32.f32 %0, %1;" : "=r"(r) : "f"(f));
    return r;
}
__device__ __forceinline__ uint32_t ldtf(const float* p) { return f2tf32(*p); }

__device__ __forceinline__ uint32_t pack_h2(float lo, float hi) {
    uint32_t r;
    asm("cvt.rn.f16x2.f32 %0, %1, %2;" : "=r"(r) : "f"(hi), "f"(lo));
    return r;
}

__device__ __forceinline__ void mma_tf32(float d[4],
                                         uint32_t a0, uint32_t a1, uint32_t a2, uint32_t a3,
                                         uint32_t b0, uint32_t b1) {
    asm volatile(
        "mma.sync.aligned.m16n8k8.row.col.f32.tf32.tf32.f32 "
        "{%0,%1,%2,%3}, {%4,%5,%6,%7}, {%8,%9}, {%0,%1,%2,%3};\n"
        : "+f"(d[0]), "+f"(d[1]), "+f"(d[2]), "+f"(d[3])
        : "r"(a0), "r"(a1), "r"(a2), "r"(a3), "r"(b0), "r"(b1));
}

__device__ __forceinline__ void mma_f16(float d[4],
                                        uint32_t a0, uint32_t a1, uint32_t a2, uint32_t a3,
                                        uint32_t b0, uint32_t b1) {
    asm volatile(
        "mma.sync.aligned.m16n8k16.row.col.f32.f16.f16.f32 "
        "{%0,%1,%2,%3}, {%4,%5,%6,%7}, {%8,%9}, {%0,%1,%2,%3};\n"
        : "+f"(d[0]), "+f"(d[1]), "+f"(d[2]), "+f"(d[3])
        : "r"(a0), "r"(a1), "r"(a2), "r"(a3), "r"(b0), "r"(b1));
}

__device__ __forceinline__ void cp_async16(uint32_t s, const void* g) {
    asm volatile("cp.async.cg.shared.global [%0], [%1], 16;\n" :: "r"(s), "l"(g));
}
__device__ __forceinline__ void cp_commit() { asm volatile("cp.async.commit_group;\n" ::: "memory"); }
__device__ __forceinline__ void cp_wait0()  { asm volatile("cp.async.wait_group 0;\n" ::: "memory"); }

// ---------------------------------------------------------------------------
// Projections:  C[M,N] = A[M,K] @ W[K,N] + bias[N]   (tf32 mainloop, proven)
// MODE 0: fp32 out. MODE 1: half out, normal layout. MODE 2: half out, Vt layout.
// ---------------------------------------------------------------------------
template <int MODE>
__global__ __launch_bounds__(128, 4) void gemm_bias_tc(
    const float* __restrict__ A, const float* __restrict__ W,
    const float* __restrict__ bias, void* __restrict__ Cout,
    int M, int N, int K)
{
    extern __shared__ float dsm[];
    float* As = dsm;                    // [2][128][36]
    float* Bs = dsm + 2 * 128 * 36;     // [2][32][68]
    const uint32_t abase = (uint32_t)__cvta_generic_to_shared(As);
    const uint32_t bbase = (uint32_t)__cvta_generic_to_shared(Bs);

    const int tid = threadIdx.x;
    const int wid = tid >> 5, lane = tid & 31;
    const int g = lane >> 2, tg = lane & 3;
    const int bm = blockIdx.y * 128, bn = blockIdx.x * 64;
    const int wm = (wid >> 1) * 64, wn = (wid & 1) * 32;

    float acc[4][4][4];
    #pragma unroll
    for (int mt = 0; mt < 4; mt++)
        #pragma unroll
        for (int nt = 0; nt < 4; nt++)
            #pragma unroll
            for (int r = 0; r < 4; r++) acc[mt][nt][r] = 0.f;

    auto load_stage = [&](int buf, int k0) {
        uint32_t ab = abase + (uint32_t)buf * 128 * 36 * 4;
        #pragma unroll
        for (int i = tid; i < 128 * 8; i += 128) {
            int r = i >> 3, seg = i & 7;
            cp_async16(ab + (r * 36 + seg * 4) * 4,
                       A + (size_t)(bm + r) * K + k0 + seg * 4);
        }
        uint32_t bb = bbase + (uint32_t)buf * 32 * 68 * 4;
        #pragma unroll
        for (int i = tid; i < 32 * 16; i += 128) {
            int r = i >> 4, seg = i & 15;
            cp_async16(bb + (r * 68 + seg * 4) * 4,
                       W + (size_t)(k0 + r) * N + bn + seg * 4);
        }
        cp_commit();
    };

    load_stage(0, 0);
    int buf = 0;
    for (int k0 = 0; k0 < K; k0 += 32, buf ^= 1) {
        cp_wait0();
        __syncthreads();
        if (k0 + 32 < K) load_stage(buf ^ 1, k0 + 32);

        const float* Ab = As + buf * 128 * 36;
        const float* Bb = Bs + buf * 32 * 68;
        #pragma unroll
        for (int ks = 0; ks < 4; ks++) {
            const int kk = ks * 8;
            uint32_t a[4][4], bf[4][2];
            #pragma unroll
            for (int mt = 0; mt < 4; mt++) {
                int mr = wm + mt * 16;
                a[mt][0] = ldtf(Ab + (mr + g) * 36 + kk + tg);
                a[mt][1] = ldtf(Ab + (mr + g + 8) * 36 + kk + tg);
                a[mt][2] = ldtf(Ab + (mr + g) * 36 + kk + tg + 4);
                a[mt][3] = ldtf(Ab + (mr + g + 8) * 36 + kk + tg + 4);
            }
            #pragma unroll
            for (int nt = 0; nt < 4; nt++) {
                int nc = wn + nt * 8 + g;
                bf[nt][0] = ldtf(Bb + (kk + tg) * 68 + nc);
                bf[nt][1] = ldtf(Bb + (kk + tg + 4) * 68 + nc);
            }
            #pragma unroll
            for (int mt = 0; mt < 4; mt++)
                #pragma unroll
                for (int nt = 0; nt < 4; nt++)
                    mma_tf32(acc[mt][nt], a[mt][0], a[mt][1], a[mt][2], a[mt][3],
                             bf[nt][0], bf[nt][1]);
        }
    }

    #pragma unroll
    for (int mt = 0; mt < 4; mt++) {
        #pragma unroll
        for (int nt = 0; nt < 4; nt++) {
            int n0 = bn + wn + nt * 8 + tg * 2;
            float b0v = bias[n0], b1v = bias[n0 + 1];
            int r0 = bm + wm + mt * 16 + g;
            float v00 = acc[mt][nt][0] + b0v, v01 = acc[mt][nt][1] + b1v;
            float v10 = acc[mt][nt][2] + b0v, v11 = acc[mt][nt][3] + b1v;
            if (MODE == 0) {
                float* C = (float*)Cout;
                C[(size_t)r0 * N + n0]           = v00;
                C[(size_t)r0 * N + n0 + 1]       = v01;
                C[(size_t)(r0 + 8) * N + n0]     = v10;
                C[(size_t)(r0 + 8) * N + n0 + 1] = v11;
            } else if (MODE == 1) {
                __half* C = (__half*)Cout;
                C[(size_t)r0 * N + n0]           = __float2half(v00);
                C[(size_t)r0 * N + n0 + 1]       = __float2half(v01);
                C[(size_t)(r0 + 8) * N + n0]     = __float2half(v10);
                C[(size_t)(r0 + 8) * N + n0 + 1] = __float2half(v11);
            } else {
                __half* C = (__half*)Cout;
                int h0 = n0 >> 6, d0 = n0 & 63;
                int b0i = r0 >> 11, t0i = r0 & 2047;
                size_t base0 = ((size_t)(b0i * 8 + h0) * 64 + d0) * 2048;
                C[base0 + t0i]            = __float2half(v00);
                C[base0 + 2048 + t0i]     = __float2half(v01);
                C[base0 + t0i + 8]        = __float2half(v10);
                C[base0 + 2048 + t0i + 8] = __float2half(v11);
            }
        }
    }
}

// ---------------------------------------------------------------------------
// Scores (fp16 mma): attn[b,h,t,s] = (Q.K)/8 + mask, kpm==0 -> -inf
// Block 128(t) x 128(s), 8 warps (2x4), single-shot K=64.
// Epilogue: fragments -> smem E[128][136] (conflict-free STS.64), then a fully
// COALESCED pass per row: LDS.128 E + LDG.128 mask + int4 kpm + STG.128 attn.
// Dynamic smem: mainloop Qs/Ks (36864B half) overlaid by E (69632B fp32).
// ---------------------------------------------------------------------------
#define EPAD 136

__global__ __launch_bounds__(256, 2) void score_h(
    const __half* __restrict__ Q, const __half* __restrict__ Kp,
    const float* __restrict__ attn_mask, const int* __restrict__ kpm,
    float* __restrict__ attn)
{
    extern __shared__ float dsm[];
    __half* Qs = (__half*)dsm;            // [128][72] half
    __half* Ks = Qs + 128 * 72;           // [128][72] half
    float*  Es = dsm;                     // [128][136] fp32 (overlays Q/K)
    const uint32_t qbase = (uint32_t)__cvta_generic_to_shared(Qs);
    const uint32_t kbase = (uint32_t)__cvta_generic_to_shared(Ks);

    const int tid = threadIdx.x;
    const int wid = tid >> 5, lane = tid & 31;
    const int g = lane >> 2, tg = lane & 3;
    const int bh = blockIdx.z;
    const int b = bh >> 3, h = bh & 7;
    const int t0 = blockIdx.y * 128, s0 = blockIdx.x * 128;
    const int wm = (wid >> 2) * 64, wn = (wid & 3) * 32;

    // Load Q,K tiles: 128 rows x 128B (64 halves) = 8 segs of 16B each.
    #pragma unroll
    for (int i = tid; i < 128 * 8; i += 256) {
        int r = i >> 3, seg = i & 7;
        cp_async16(qbase + (r * 72 + seg * 8) * 2,
                   Q + (size_t)(b * T_ + t0 + r) * DQ_ + h * HD_ + seg * 8);
        cp_async16(kbase + (r * 72 + seg * 8) * 2,
                   Kp + (size_t)(b * S_ + s0 + r) * DQ_ + h * HD_ + seg * 8);
    }
    cp_commit();
    cp_wait0();
    __syncthreads();

    float acc[4][4][4];
    #pragma unroll
    for (int mt = 0; mt < 4; mt++)
        #pragma unroll
        for (int nt = 0; nt < 4; nt++)
            #pragma unroll
            for (int r = 0; r < 4; r++) acc[mt][nt][r] = 0.f;

    #pragma unroll
    for (int ks = 0; ks < 4; ks++) {
        const int kk = ks * 16;
        uint32_t a[4][4], bf[4][2];
        #pragma unroll
        for (int mt = 0; mt < 4; mt++) {
            int mr = wm + mt * 16;
            a[mt][0] = *(const uint32_t*)(Qs + (mr + g) * 72 + kk + 2 * tg);
            a[mt][1] = *(const uint32_t*)(Qs + (mr + g + 8) * 72 + kk + 2 * tg);
            a[mt][2] = *(const uint32_t*)(Qs + (mr + g) * 72 + kk + 8 + 2 * tg);
            a[mt][3] = *(const uint32_t*)(Qs + (mr + g + 8) * 72 + kk + 8 + 2 * tg);
        }
        #pragma unroll
        for (int nt = 0; nt < 4; nt++) {
            int nc = wn + nt * 8 + g;
            bf[nt][0] = *(const uint32_t*)(Ks + nc * 72 + kk + 2 * tg);
            bf[nt][1] = *(const uint32_t*)(Ks + nc * 72 + kk + 8 + 2 * tg);
        }
        #pragma unroll
        for (int mt = 0; mt < 4; mt++)
            #pragma unroll
            for (int nt = 0; nt < 4; nt++)
                mma_f16(acc[mt][nt], a[mt][0], a[mt][1], a[mt][2], a[mt][3],
                        bf[nt][0], bf[nt][1]);
    }

    // All warps done reading Q/K smem before E overlays it.
    __syncthreads();

    // Stage raw scaled scores to smem (STS.64, stride 136 -> conflict-free).
    #pragma unroll
    for (int mt = 0; mt < 4; mt++) {
        #pragma unroll
        for (int half = 0; half < 2; half++) {
            int rloc = wm + mt * 16 + half * 8 + g;
            #pragma unroll
            for (int nt = 0; nt < 4; nt++) {
                int sc = wn + nt * 8 + tg * 2;
                *(float2*)(Es + rloc * EPAD + sc) =
                    make_float2(acc[mt][nt][half * 2] * 0.125f,
                                acc[mt][nt][half * 2 + 1] * 0.125f);
            }
        }
    }
    __syncthreads();

    // Coalesced pass: warp w owns rows w, w+8, ... Each lane handles 4 cols.
    const int c4 = lane * 4;
    int4 kp = *(const int4*)(kpm + b * S_ + s0 + c4);
    float4 nif = make_float4(kp.x == 0 ? -INFINITY : 0.f,
                             kp.y == 0 ? -INFINITY : 0.f,
                             kp.z == 0 ? -INFINITY : 0.f,
                             kp.w == 0 ? -INFINITY : 0.f);
    float* arow = attn + ((size_t)bh * T_ + t0) * S_ + s0;
    #pragma unroll
    for (int rr = 0; rr < 16; rr++) {
        int r = wid + rr * 8;
        float4 e = *(const float4*)(Es + r * EPAD + c4);
        float4 m = *(const float4*)(attn_mask + (size_t)(t0 + r) * S_ + s0 + c4);
        float4 v;
        v.x = kp.x == 0 ? nif.x : e.x + m.x;
        v.y = kp.y == 0 ? nif.y : e.y + m.y;
        v.z = kp.z == 0 ? nif.z : e.z + m.z;
        v.w = kp.w == 0 ? nif.w : e.w + m.w;
        *(float4*)(arow + (size_t)r * S_ + c4) = v;
    }
}

// ---------------------------------------------------------------------------
// In-place row softmax over S=2048 (proven).
// ---------------------------------------------------------------------------
__global__ __launch_bounds__(256) void softmax_kernel(float* __restrict__ attn)
{
    size_t row = blockIdx.x;
    float* p = attn + row * (size_t)S_;
    int tid = threadIdx.x;

    float v[8];
    #pragma unroll
    for (int i = 0; i < 8; i++) v[i] = p[tid + 256 * i];

    float m = v[0];
    #pragma unroll
    for (int i = 1; i < 8; i++) m = fmaxf(m, v[i]);
    #pragma unroll
    for (int o = 16; o > 0; o >>= 1) m = fmaxf(m, __shfl_xor_sync(0xffffffffu, m, o));

    __shared__ float red[8];
    if ((tid & 31) == 0) red[tid >> 5] = m;
    __syncthreads();
    if (tid < 32) {
        float x = (tid < 8) ? red[tid] : -INFINITY;
        #pragma unroll
        for (int o = 4; o > 0; o >>= 1) x = fmaxf(x, __shfl_xor_sync(0xffffffffu, x, o));
        if (tid == 0) red[0] = x;
    }
    __syncthreads();
    m = red[0];
    __syncthreads();

    float s = 0.f;
    #pragma unroll
    for (int i = 0; i < 8; i++) { v[i] = __expf(v[i] - m); s += v[i]; }
    #pragma unroll
    for (int o = 16; o > 0; o >>= 1) s += __shfl_xor_sync(0xffffffffu, s, o);
    if ((tid & 31) == 0) red[tid >> 5] = s;
    __syncthreads();
    if (tid < 32) {
        float x = (tid < 8) ? red[tid] : 0.f;
        #pragma unroll
        for (int o = 4; o > 0; o >>= 1) x += __shfl_xor_sync(0xffffffffu, x, o);
        if (tid == 0) red[0] = x;
    }
    __syncthreads();
    float inv = 1.0f / red[0];

    #pragma unroll
    for (int i = 0; i < 8; i++) p[tid + 256 * i] = v[i] * inv;
}

// ---------------------------------------------------------------------------
// AV (fp16 mma, proven): ctx[b,t,h,:] = attn[b,h,t,:] @ V[b,:,h,:]
// ---------------------------------------------------------------------------
__global__ __launch_bounds__(128, 4) void av_h(
    const float* __restrict__ attn, const __half* __restrict__ Vt,
    float* __restrict__ ctx)
{
    extern __shared__ float dsm[];
    float* As = dsm;                                   // [2][128][40] fp32
    __half* Vs = (__half*)(dsm + 2 * 128 * 40);        // [2][64][40] half
    const uint32_t abase = (uint32_t)__cvta_generic_to_shared(As);
    const uint32_t vbase = (uint32_t)__cvta_generic_to_shared(Vs);

    const int tid = threadIdx.x;
    const int wid = tid >> 5, lane = tid & 31;
    const int g = lane >> 2, tg = lane & 3;
    const int bh = blockIdx.y;
    const int t0 = blockIdx.x * 128;
    const int wm = (wid >> 1) * 64, wn = (wid & 1) * 32;

    const float* arow = attn + ((size_t)bh * T_ + t0) * S_;
    const __half* vrow = Vt + (size_t)bh * HD_ * S_;

    float acc[4][4][4];
    #pragma unroll
    for (int mt = 0; mt < 4; mt++)
        #pragma unroll
        for (int nt = 0; nt < 4; nt++)
            #pragma unroll
            for (int r = 0; r < 4; r++) acc[mt][nt][r] = 0.f;

    auto load_stage = [&](int buf, int k0) {
        uint32_t ab = abase + (uint32_t)buf * 128 * 40 * 4;
        #pragma unroll
        for (int i = tid; i < 128 * 8; i += 128) {
            int r = i >> 3, seg = i & 7;
            cp_async16(ab + (r * 40 + seg * 4) * 4,
                       arow + (size_t)r * S_ + k0 + seg * 4);
        }
        uint32_t vb = vbase + (uint32_t)buf * 64 * 40 * 2;
        #pragma unroll
        for (int i = tid; i < 64 * 4; i += 128) {
            int r = i >> 2, seg = i & 3;
            cp_async16(vb + (r * 40 + seg * 8) * 2,
                       vrow + (size_t)r * S_ + k0 + seg * 8);
        }
        cp_commit();
    };

    load_stage(0, 0);
    int buf = 0;
    for (int k0 = 0; k0 < S_; k0 += 32, buf ^= 1) {
        cp_wait0();
        __syncthreads();
        if (k0 + 32 < S_) load_stage(buf ^ 1, k0 + 32);

        const float* Ab = As + buf * 128 * 40;
        const __half* Vb = Vs + buf * 64 * 40;
        #pragma unroll
        for (int ks = 0; ks < 2; ks++) {
            const int kk = ks * 16;
            uint32_t a[4][4], bf[4][2];
            #pragma unroll
            for (int mt = 0; mt < 4; mt++) {
                int mr = wm + mt * 16;
                float2 p0 = *(const float2*)(Ab + (mr + g) * 40 + kk + 2 * tg);
                float2 p1 = *(const float2*)(Ab + (mr + g + 8) * 40 + kk + 2 * tg);
                float2 p2 = *(const float2*)(Ab + (mr + g) * 40 + kk + 8 + 2 * tg);
                float2 p3 = *(const float2*)(Ab + (mr + g + 8) * 40 + kk + 8 + 2 * tg);
                a[mt][0] = pack_h2(p0.x, p0.y);
                a[mt][1] = pack_h2(p1.x, p1.y);
                a[mt][2] = pack_h2(p2.x, p2.y);
                a[mt][3] = pack_h2(p3.x, p3.y);
            }
            #pragma unroll
            for (int nt = 0; nt < 4; nt++) {
                int nc = wn + nt * 8 + g;
                bf[nt][0] = *(const uint32_t*)(Vb + nc * 40 + kk + 2 * tg);
                bf[nt][1] = *(const uint32_t*)(Vb + nc * 40 + kk + 8 + 2 * tg);
            }
            #pragma unroll
            for (int mt = 0; mt < 4; mt++)
                #pragma unroll
                for (int nt = 0; nt < 4; nt++)
                    mma_f16(acc[mt][nt], a[mt][0], a[mt][1], a[mt][2], a[mt][3],
                            bf[nt][0], bf[nt][1]);
        }
        __syncthreads();
    }

    const int b = bh >> 3, h = bh & 7;
    #pragma unroll
    for (int mt = 0; mt < 4; mt++) {
        #pragma unroll
        for (int nt = 0; nt < 4; nt++) {
            int d0 = wn + nt * 8 + tg * 2;
            int t = t0 + wm + mt * 16 + g;
            ctx[(size_t)(b * T_ + t) * DQ_ + h * HD_ + d0]         = acc[mt][nt][0];
            ctx[(size_t)(b * T_ + t) * DQ_ + h * HD_ + d0 + 1]     = acc[mt][nt][1];
            ctx[(size_t)(b * T_ + t + 8) * DQ_ + h * HD_ + d0]     = acc[mt][nt][2];
            ctx[(size_t)(b * T_ + t + 8) * DQ_ + h * HD_ + d0 + 1] = acc[mt][nt][3];
        }
    }
}

// ---------------------------------------------------------------------------
// Launch (single stream)
// ---------------------------------------------------------------------------
extern "C" void kernel_launch(void* const* d_in, const int* in_sizes, int n_in,
                              void* d_out, int out_size)
{
    const float* query     = (const float*)d_in[0];
    const float* key       = (const float*)d_in[1];
    const float* value     = (const float*)d_in[2];
    const int*   kpm       = (const int*)  d_in[3];
    const float* attn_mask = (const float*)d_in[4];
    const float* Wq = (const float*)d_in[5];
    const float* bq = (const float*)d_in[6];
    const float* Wk = (const float*)d_in[7];
    const float* bk = (const float*)d_in[8];
    const float* Wv = (const float*)d_in[9];
    const float* bv = (const float*)d_in[10];
    const float* Wo = (const float*)d_in[11];
    const float* bo = (const float*)d_in[12];

    float* out  = (float*)d_out;                        // [B,T,DQ]
    float* attn = out + (size_t)B_ * T_ * DQ_;          // [B,H,T,S]

    __half *Qh, *Kh, *Vt;
    float *Cp;
    cudaGetSymbolAddress((void**)&Qh, g_Qh);
    cudaGetSymbolAddress((void**)&Kh, g_Kh);
    cudaGetSymbolAddress((void**)&Vt, g_Vt);
    cudaGetSymbolAddress((void**)&Cp, g_ctx);

    const int GEMM_SMEM  = (2 * 128 * 36 + 2 * 32 * 68) * 4;   // 54272
    const int AV_SMEM    = 2 * 128 * 40 * 4 + 2 * 64 * 40 * 2; // 51200
    const int SCORE_SMEM = 128 * EPAD * 4;                      // 69632 (E overlays Q/K)

    static int attr_done = 0;
    if (!attr_done) {
        cudaFuncSetAttribute(gemm_bias_tc<0>, cudaFuncAttributeMaxDynamicSharedMemorySize, GEMM_SMEM);
        cudaFuncSetAttribute(gemm_bias_tc<1>, cudaFuncAttributeMaxDynamicSharedMemorySize, GEMM_SMEM);
        cudaFuncSetAttribute(gemm_bias_tc<2>, cudaFuncAttributeMaxDynamicSharedMemorySize, GEMM_SMEM);
        cudaFuncSetAttribute(score_h,         cudaFuncAttributeMaxDynamicSharedMemorySize, SCORE_SMEM);
        cudaFuncSetAttribute(av_h,            cudaFuncAttributeMaxDynamicSharedMemorySize, AV_SMEM);
        attr_done = 1;
    }

    const int M = B_ * T_;   // 8192

    // Projections: Q,K -> half; V -> half transposed
    gemm_bias_tc<1><<<dim3(DQ_ / 64, M / 128), 128, GEMM_SMEM>>>(query, Wq, bq, Qh, M, DQ_, DQ_);
    gemm_bias_tc<1><<<dim3(DQ_ / 64, M / 128), 128, GEMM_SMEM>>>(key,   Wk, bk, Kh, M, DQ_, DKV_);
    gemm_bias_tc<2><<<dim3(DQ_ / 64, M / 128), 128, GEMM_SMEM>>>(value, Wv, bv, Vt, M, DQ_, DKV_);

    // Scores + mask -> attn region of d_out (fp16 mma, coalesced epilogue)
    score_h<<<dim3(S_ / 128, T_ / 128, B_ * H_), 256, SCORE_SMEM>>>(Qh, Kh, attn_mask, kpm, attn);

    // Row softmax in place
    softmax_kernel<<<B_ * H_ * T_, 256>>>(attn);

    // attn @ V -> ctx (fp16 mma, transposed-V tiles)
    av_h<<<dim3(T_ / 128, B_ * H_), 128, AV_SMEM>>>(attn, Vt, Cp);

    // Output projection (fp32 out)
    gemm_bias_tc<0><<<dim3(DQ_ / 64, M / 128), 128, GEMM_SMEM>>>(Cp, Wo, bo, out, M, DQ_, DQ_);
}